// round 13
// baseline (speedup 1.0000x reference)
#include <cuda_runtime.h>
#include <cuda_bf16.h>
#include <mma.h>
#include <stdint.h>

using namespace nvcuda;

// Problem constants (fixed benchmark): N=1e6, IN_C=OUT_C=64, FEAT_C=128, G=4096
#define N_MAX 1000000
#define G_MAX 4096

__device__ int      d_count[G_MAX];
__device__ int      d_offsets[G_MAX + 1];
__device__ int      d_rank[N_MAX];
__device__ int      d_order[N_MAX];
__device__ float    d_mu[G_MAX * 64];
__device__ float    d_sig[G_MAX * 64];
// bf16 hi/lo images of W_fc [64k][64n], packed as bf16-pairs along n: [k][32] u32
__device__ uint32_t d_Wh32[2048];
__device__ uint32_t d_Wl32[2048];

// ---------------------------------------------------------------------------
// Preprocessing (unchanged from round 12)
// ---------------------------------------------------------------------------
__global__ void musig_init_kernel(const float* __restrict__ feat,
                                  const float* __restrict__ Wmu, const float* __restrict__ bmu,
                                  const float* __restrict__ Wsg, const float* __restrict__ bsg,
                                  const float* __restrict__ Wfc, int G) {
    int gid = blockIdx.x * blockDim.x + threadIdx.x;
    if (gid < G) d_count[gid] = 0;
    if (gid < 2048) {  // pair (k, 2j)/(k, 2j+1)
        int k = gid >> 5, j = gid & 31;
        float w0 = Wfc[k * 64 + 2 * j];
        float w1 = Wfc[k * 64 + 2 * j + 1];
        __nv_bfloat16 h0 = __float2bfloat16(w0);
        __nv_bfloat16 h1 = __float2bfloat16(w1);
        __nv_bfloat16 l0 = __float2bfloat16(w0 - __bfloat162float(h0));
        __nv_bfloat16 l1 = __float2bfloat16(w1 - __bfloat162float(h1));
        d_Wh32[gid] = (uint32_t)__bfloat16_as_ushort(h0) | ((uint32_t)__bfloat16_as_ushort(h1) << 16);
        d_Wl32[gid] = (uint32_t)__bfloat16_as_ushort(l0) | ((uint32_t)__bfloat16_as_ushort(l1) << 16);
    }

    __shared__ float sF[4][128];
    int t  = threadIdx.x;
    int g0 = blockIdx.x * 4;
    for (int i = t; i < 512; i += 256) {
        int gl = i >> 7, k = i & 127;
        int g  = g0 + gl;
        sF[gl][k] = (g < G) ? feat[(size_t)g * 128 + k] : 0.f;
    }
    __syncthreads();
    int gl = t >> 6, c = t & 63;
    int g  = g0 + gl;
    if (g >= G) return;
    float am = bmu[c], as = bsg[c];
#pragma unroll 4
    for (int k = 0; k < 128; k++) {
        float f = sF[gl][k];
        am = fmaf(f, Wmu[k * 64 + c], am);
        as = fmaf(f, Wsg[k * 64 + c], as);
    }
    d_mu[(size_t)g * 64 + c]  = am;
    d_sig[(size_t)g * 64 + c] = as;
}

// histogram; atomic's return value IS the row's rank within its group
__global__ void hist_kernel(const int* __restrict__ seg, int n) {
    int i = blockIdx.x * blockDim.x + threadIdx.x;
    int base = i * 4;
    if (base + 3 < n) {
        int4 s = *reinterpret_cast<const int4*>(seg + base);
        int r0 = atomicAdd(&d_count[s.x], 1);
        int r1 = atomicAdd(&d_count[s.y], 1);
        int r2 = atomicAdd(&d_count[s.z], 1);
        int r3 = atomicAdd(&d_count[s.w], 1);
        *reinterpret_cast<int4*>(d_rank + base) = make_int4(r0, r1, r2, r3);
    } else {
        for (int j = base; j < n; j++)
            d_rank[j] = atomicAdd(&d_count[seg[j]], 1);
    }
}

__global__ void scan_kernel(int G) {
    __shared__ int wsum[32];
    __shared__ int wpre[32];
    const unsigned full = 0xffffffffu;
    int t = threadIdx.x, lane = t & 31, w = t >> 5;
    int v[4];
    int s = 0;
#pragma unroll
    for (int i = 0; i < 4; i++) {
        int g = 4 * t + i;
        v[i] = (g < G) ? d_count[g] : 0;
        s += v[i];
    }
    int sc = s;
#pragma unroll
    for (int off = 1; off < 32; off <<= 1) {
        int o = __shfl_up_sync(full, sc, off);
        if (lane >= off) sc += o;
    }
    if (lane == 31) wsum[w] = sc;
    __syncthreads();
    if (w == 0) {
        int ws = wsum[lane];
        int p = ws;
#pragma unroll
        for (int off = 1; off < 32; off <<= 1) {
            int o = __shfl_up_sync(full, p, off);
            if (lane >= off) p += o;
        }
        wpre[lane] = p - ws;
    }
    __syncthreads();
    int excl = wpre[w] + sc - s;
#pragma unroll
    for (int i = 0; i < 4; i++) {
        int g = 4 * t + i;
        if (g < G) {
            d_offsets[g] = excl;
            excl += v[i];
        }
    }
    if (t == 1023) d_offsets[G] = excl;
}

// no atomic: position = group offset + precomputed rank
__global__ void scatter_kernel(const int* __restrict__ seg, int n) {
    int i = blockIdx.x * blockDim.x + threadIdx.x;
    int base = i * 4;
    if (base + 3 < n) {
        int4 s = *reinterpret_cast<const int4*>(seg + base);
        int4 r = *reinterpret_cast<const int4*>(d_rank + base);
        d_order[d_offsets[s.x] + r.x] = base;
        d_order[d_offsets[s.y] + r.y] = base + 1;
        d_order[d_offsets[s.z] + r.z] = base + 2;
        d_order[d_offsets[s.w] + r.w] = base + 3;
    } else {
        for (int j = base; j < n; j++)
            d_order[d_offsets[seg[j]] + d_rank[j]] = j;
    }
}

// ---------------------------------------------------------------------------
// Group kernel v3: wmma bf16 3-split GEMM + fused AdaIN, RECOMPUTE-APPLY.
// 256 threads (8 warps), chunk = 128 rows, NO h cache -> smem 91KB -> 2 CTAs/SM.
// Pass A: stage -> GEMM -> per-channel stats in registers (h discarded).
// Pass B: re-stage -> re-GEMM -> scale/shift + ReLU -> direct STG.
// b_fc cancels after normalization -> D = x @ W only.
// SMEM (bytes):
//   0     : sSum[64], sSq[64], sScale[64], sShift[64]   (1024)
//   1024  : Wh 64*72 bf16   (9216)
//   10240 : Wl               (9216)
//   19456 : Ah 128*72 bf16  (18432)
//   37888 : Al              (18432)
//   56320 : sH 128*72 f32   (36864)   total 93184
// ---------------------------------------------------------------------------
#define LDA   72
#define CHUNK 128
#define SM_WH 1024
#define SM_WL 10240
#define SM_AH 19456
#define SM_AL 37888
#define SM_H  56320
#define SMEM_BYTES 93184
#define NTHREADS 256

typedef wmma::fragment<wmma::matrix_a, 16, 16, 16, __nv_bfloat16, wmma::row_major> FragA;
typedef wmma::fragment<wmma::matrix_b, 16, 16, 16, __nv_bfloat16, wmma::row_major> FragB;
typedef wmma::fragment<wmma::accumulator, 16, 16, 16, float> FragC;

// stage local row sr (0..127), half sq (32 cols): group row = base+sr; >=cnt -> 0
__device__ __forceinline__ void stage_half(const float* __restrict__ x,
                                           char* __restrict__ smem,
                                           int off, int base, int cnt,
                                           int sr, int sq) {
    float4 v[8];
    int grow = base + sr;
    if (grow < cnt) {
        int gi = __ldg(&d_order[off + grow]);
        const float4* xr = reinterpret_cast<const float4*>(x + (size_t)gi * 64 + 32 * sq);
#pragma unroll
        for (int i = 0; i < 8; i++) v[i] = xr[i];
    } else {
#pragma unroll
        for (int i = 0; i < 8; i++) v[i] = make_float4(0.f, 0.f, 0.f, 0.f);
    }
    uint32_t uh[16], ul[16];
#pragma unroll
    for (int i = 0; i < 8; i++) {
        float f0 = v[i].x, f1 = v[i].y, f2 = v[i].z, f3 = v[i].w;
        __nv_bfloat16 h0 = __float2bfloat16(f0), h1 = __float2bfloat16(f1);
        __nv_bfloat16 h2 = __float2bfloat16(f2), h3 = __float2bfloat16(f3);
        __nv_bfloat16 l0 = __float2bfloat16(f0 - __bfloat162float(h0));
        __nv_bfloat16 l1 = __float2bfloat16(f1 - __bfloat162float(h1));
        __nv_bfloat16 l2 = __float2bfloat16(f2 - __bfloat162float(h2));
        __nv_bfloat16 l3 = __float2bfloat16(f3 - __bfloat162float(h3));
        uh[2 * i]     = (uint32_t)__bfloat16_as_ushort(h0) | ((uint32_t)__bfloat16_as_ushort(h1) << 16);
        uh[2 * i + 1] = (uint32_t)__bfloat16_as_ushort(h2) | ((uint32_t)__bfloat16_as_ushort(h3) << 16);
        ul[2 * i]     = (uint32_t)__bfloat16_as_ushort(l0) | ((uint32_t)__bfloat16_as_ushort(l1) << 16);
        ul[2 * i + 1] = (uint32_t)__bfloat16_as_ushort(l2) | ((uint32_t)__bfloat16_as_ushort(l3) << 16);
    }
    int b2 = sr * (LDA * 2) + 64 * sq;
    char* Ah = smem + SM_AH + b2;
    char* Al = smem + SM_AL + b2;
#pragma unroll
    for (int i = 0; i < 4; i++) {
        *reinterpret_cast<uint4*>(Ah + 16 * i) =
            make_uint4(uh[4 * i], uh[4 * i + 1], uh[4 * i + 2], uh[4 * i + 3]);
        *reinterpret_cast<uint4*>(Al + 16 * i) =
            make_uint4(ul[4 * i], ul[4 * i + 1], ul[4 * i + 2], ul[4 * i + 3]);
    }
}

// warp `tile` (0..7): 3-split GEMM of A rows [16*tile,16*tile+16) -> sH
__device__ __forceinline__ void gemm_tile(char* __restrict__ smem, int tile) {
    const __nv_bfloat16* Ah = reinterpret_cast<const __nv_bfloat16*>(smem + SM_AH);
    const __nv_bfloat16* Al = reinterpret_cast<const __nv_bfloat16*>(smem + SM_AL);
    const __nv_bfloat16* Wh = reinterpret_cast<const __nv_bfloat16*>(smem + SM_WH);
    const __nv_bfloat16* Wl = reinterpret_cast<const __nv_bfloat16*>(smem + SM_WL);
    float* sH = reinterpret_cast<float*>(smem + SM_H);

    FragA a[4];
    FragC acc[4];
#pragma unroll
    for (int ct = 0; ct < 4; ct++) wmma::fill_fragment(acc[ct], 0.f);
#pragma unroll
    for (int s = 0; s < 3; s++) {
        const __nv_bfloat16* A = (s < 2) ? Ah : Al;
        const __nv_bfloat16* B = (s == 1) ? Wl : Wh;
        if (s != 1) {  // s==1 reuses s==0's A fragments
#pragma unroll
            for (int k4 = 0; k4 < 4; k4++)
                wmma::load_matrix_sync(a[k4], A + (size_t)(16 * tile) * LDA + 16 * k4, LDA);
        }
#pragma unroll
        for (int ct = 0; ct < 4; ct++) {
#pragma unroll
            for (int k4 = 0; k4 < 4; k4++) {
                FragB b;
                wmma::load_matrix_sync(b, B + (size_t)(16 * k4) * LDA + 16 * ct, LDA);
                wmma::mma_sync(acc[ct], a[k4], b, acc[ct]);
            }
        }
    }
#pragma unroll
    for (int ct = 0; ct < 4; ct++)
        wmma::store_matrix_sync(sH + (size_t)(16 * tile) * LDA + 16 * ct, acc[ct],
                                LDA, wmma::mem_row_major);
}

__global__ __launch_bounds__(NTHREADS, 2) void group_kernel(const float* __restrict__ x,
                                                            float* __restrict__ out) {
    extern __shared__ char smem[];
    float* sSum   = reinterpret_cast<float*>(smem);
    float* sSq    = sSum + 64;
    float* sScale = sSq + 64;
    float* sShift = sScale + 64;
    float* sH     = reinterpret_cast<float*>(smem + SM_H);

    int t = threadIdx.x, w = t >> 5, lane = t & 31;
    int g   = blockIdx.x;
    int off = d_offsets[g];
    int cnt = d_offsets[g + 1] - off;
    if (cnt == 0) return;

    // W hi/lo -> padded smem (stride 72 bf16)
    for (int i = t; i < 2048; i += NTHREADS) {
        int k = i >> 5, j = i & 31;
        int b2 = k * (LDA * 2) + 4 * j;
        *reinterpret_cast<uint32_t*>(smem + SM_WH + b2) = d_Wh32[i];
        *reinterpret_cast<uint32_t*>(smem + SM_WL + b2) = d_Wl32[i];
    }
    if (t < 64) { sSum[t] = 0.f; sSq[t] = 0.f; }

    int nch = (cnt + CHUNK - 1) >> 7;
    int sr = t >> 1, sq = t & 1;      // staging coords
    int qr = t >> 6, cc = t & 63;     // stats coords: rows qr*32.., channel cc

    // ---------------- pass A: GEMM + stats (h discarded) ----------------
    float acc1 = 0.f, acc2 = 0.f;
    for (int c = 0; c < nch; c++) {
        int base = c << 7;
        stage_half(x, smem, off, base, cnt, sr, sq);
        __syncthreads();
        gemm_tile(smem, w);
        __syncthreads();
        int lim = cnt - base;
        if (lim > 128) lim = 128;
        for (int r = qr * 32; r < qr * 32 + 32; r++) {
            if (r < lim) {
                float h = sH[(size_t)r * LDA + cc];
                acc1 += h;
                acc2 = fmaf(h, h, acc2);
            }
        }
        __syncthreads();   // stats read done before next chunk overwrites sH
    }
    atomicAdd(&sSum[cc], acc1);
    atomicAdd(&sSq[cc],  acc2);
    __syncthreads();

    if (t < 64) {
        float inv  = 1.0f / (float)cnt;
        float mean = sSum[t] * inv;
        float var  = fmaxf(sSq[t] * inv - mean * mean, 0.f);
        float sc   = __ldg(&d_sig[(size_t)g * 64 + t]) * rsqrtf(var + 1e-14f);
        sScale[t] = sc;
        sShift[t] = __ldg(&d_mu[(size_t)g * 64 + t]) - mean * sc;
    }
    __syncthreads();

    float2 sc2 = reinterpret_cast<float2*>(sScale)[lane];
    float2 sh2 = reinterpret_cast<float2*>(sShift)[lane];

    // ---------------- pass B: recompute + apply + write ----------------
    for (int c = 0; c < nch; c++) {
        int base = c << 7;
        stage_half(x, smem, off, base, cnt, sr, sq);
        __syncthreads();
        gemm_tile(smem, w);
        __syncthreads();
        // warp w handles rows w*16 .. w*16+15 of this chunk
        for (int r = w * 16; r < w * 16 + 16; r++) {
            int gr = base + r;
            if (gr < cnt) {
                int gi = __ldg(&d_order[off + gr]);
                float2 h2 = *reinterpret_cast<float2*>(&sH[(size_t)r * LDA + 2 * lane]);
                float2 o;
                o.x = fmaxf(fmaf(h2.x, sc2.x, sh2.x), 0.f);
                o.y = fmaxf(fmaf(h2.y, sc2.y, sh2.y), 0.f);
                reinterpret_cast<float2*>(out + (size_t)gi * 64)[lane] = o;
            }
        }
        __syncthreads();   // writes done before next chunk overwrites sH
    }
}

// ---------------------------------------------------------------------------
extern "C" void kernel_launch(void* const* d_in, const int* in_sizes, int n_in,
                              void* d_out, int out_size) {
    int wi = (n_in >= 10) ? 4 : 3;
    const float* x    = (const float*)d_in[0];
    const float* feat = (const float*)d_in[1];
    const int*   seg  = (const int*)d_in[2];
    const float* Wfc  = (const float*)d_in[wi + 0];
    const float* Wmu  = (const float*)d_in[wi + 2];
    const float* bmu  = (const float*)d_in[wi + 3];
    const float* Wsg  = (const float*)d_in[wi + 4];
    const float* bsg  = (const float*)d_in[wi + 5];
    float* out = (float*)d_out;

    int n = in_sizes[0] / 64;
    int G = in_sizes[1] / 128;

    cudaFuncSetAttribute(group_kernel, cudaFuncAttributeMaxDynamicSharedMemorySize,
                         SMEM_BYTES);

    int q = (n + 3) / 4;
    musig_init_kernel<<<(G + 3) / 4, 256>>>(feat, Wmu, bmu, Wsg, bsg, Wfc, G);
    hist_kernel<<<(q + 255) / 256, 256>>>(seg, n);
    scan_kernel<<<1, 1024>>>(G);
    scatter_kernel<<<(q + 255) / 256, 256>>>(seg, n);
    group_kernel<<<G, NTHREADS, SMEM_BYTES>>>(x, out);
}

// round 14
// speedup vs baseline: 1.1659x; 1.1659x over previous
#include <cuda_runtime.h>
#include <cuda_bf16.h>
#include <mma.h>
#include <stdint.h>

using namespace nvcuda;

// Problem constants (fixed benchmark): N=1e6, IN_C=OUT_C=64, FEAT_C=128, G=4096
#define N_MAX 1000000
#define G_MAX 4096

__device__ int      d_count[G_MAX];
__device__ int      d_offsets[G_MAX + 1];
__device__ int      d_rank[N_MAX];
__device__ int      d_order[N_MAX];
__device__ float    d_mu[G_MAX * 64];
__device__ float    d_sig[G_MAX * 64];
// bf16 hi/lo images of W_fc [64k][64n], packed as bf16-pairs along n: [k][32] u32
__device__ uint32_t d_Wh32[2048];
__device__ uint32_t d_Wl32[2048];
// dense h = x @ W scratch, padded to a multiple of the 128-row GEMM tile
__device__ float    d_h[(N_MAX + 256) * 64];

// ---------------------------------------------------------------------------
// Preprocessing
// ---------------------------------------------------------------------------
__global__ void musig_init_kernel(const float* __restrict__ feat,
                                  const float* __restrict__ Wmu, const float* __restrict__ bmu,
                                  const float* __restrict__ Wsg, const float* __restrict__ bsg,
                                  const float* __restrict__ Wfc, int G) {
    int gid = blockIdx.x * blockDim.x + threadIdx.x;
    if (gid < G) d_count[gid] = 0;
    if (gid < 2048) {  // pair (k, 2j)/(k, 2j+1)
        int k = gid >> 5, j = gid & 31;
        float w0 = Wfc[k * 64 + 2 * j];
        float w1 = Wfc[k * 64 + 2 * j + 1];
        __nv_bfloat16 h0 = __float2bfloat16(w0);
        __nv_bfloat16 h1 = __float2bfloat16(w1);
        __nv_bfloat16 l0 = __float2bfloat16(w0 - __bfloat162float(h0));
        __nv_bfloat16 l1 = __float2bfloat16(w1 - __bfloat162float(h1));
        d_Wh32[gid] = (uint32_t)__bfloat16_as_ushort(h0) | ((uint32_t)__bfloat16_as_ushort(h1) << 16);
        d_Wl32[gid] = (uint32_t)__bfloat16_as_ushort(l0) | ((uint32_t)__bfloat16_as_ushort(l1) << 16);
    }

    __shared__ float sF[4][128];
    int t  = threadIdx.x;
    int g0 = blockIdx.x * 4;
    for (int i = t; i < 512; i += 256) {
        int gl = i >> 7, k = i & 127;
        int g  = g0 + gl;
        sF[gl][k] = (g < G) ? feat[(size_t)g * 128 + k] : 0.f;
    }
    __syncthreads();
    int gl = t >> 6, c = t & 63;
    int g  = g0 + gl;
    if (g >= G) return;
    float am = bmu[c], as = bsg[c];
#pragma unroll 4
    for (int k = 0; k < 128; k++) {
        float f = sF[gl][k];
        am = fmaf(f, Wmu[k * 64 + c], am);
        as = fmaf(f, Wsg[k * 64 + c], as);
    }
    d_mu[(size_t)g * 64 + c]  = am;
    d_sig[(size_t)g * 64 + c] = as;
}

// histogram; atomic's return value IS the row's rank within its group
__global__ void hist_kernel(const int* __restrict__ seg, int n) {
    int i = blockIdx.x * blockDim.x + threadIdx.x;
    int base = i * 4;
    if (base + 3 < n) {
        int4 s = *reinterpret_cast<const int4*>(seg + base);
        int r0 = atomicAdd(&d_count[s.x], 1);
        int r1 = atomicAdd(&d_count[s.y], 1);
        int r2 = atomicAdd(&d_count[s.z], 1);
        int r3 = atomicAdd(&d_count[s.w], 1);
        *reinterpret_cast<int4*>(d_rank + base) = make_int4(r0, r1, r2, r3);
    } else {
        for (int j = base; j < n; j++)
            d_rank[j] = atomicAdd(&d_count[seg[j]], 1);
    }
}

__global__ void scan_kernel(int G) {
    __shared__ int wsum[32];
    __shared__ int wpre[32];
    const unsigned full = 0xffffffffu;
    int t = threadIdx.x, lane = t & 31, w = t >> 5;
    int v[4];
    int s = 0;
#pragma unroll
    for (int i = 0; i < 4; i++) {
        int g = 4 * t + i;
        v[i] = (g < G) ? d_count[g] : 0;
        s += v[i];
    }
    int sc = s;
#pragma unroll
    for (int off = 1; off < 32; off <<= 1) {
        int o = __shfl_up_sync(full, sc, off);
        if (lane >= off) sc += o;
    }
    if (lane == 31) wsum[w] = sc;
    __syncthreads();
    if (w == 0) {
        int ws = wsum[lane];
        int p = ws;
#pragma unroll
        for (int off = 1; off < 32; off <<= 1) {
            int o = __shfl_up_sync(full, p, off);
            if (lane >= off) p += o;
        }
        wpre[lane] = p - ws;
    }
    __syncthreads();
    int excl = wpre[w] + sc - s;
#pragma unroll
    for (int i = 0; i < 4; i++) {
        int g = 4 * t + i;
        if (g < G) {
            d_offsets[g] = excl;
            excl += v[i];
        }
    }
    if (t == 1023) d_offsets[G] = excl;
}

// no atomic: position = group offset + precomputed rank
__global__ void scatter_kernel(const int* __restrict__ seg, int n) {
    int i = blockIdx.x * blockDim.x + threadIdx.x;
    int base = i * 4;
    if (base + 3 < n) {
        int4 s = *reinterpret_cast<const int4*>(seg + base);
        int4 r = *reinterpret_cast<const int4*>(d_rank + base);
        d_order[d_offsets[s.x] + r.x] = base;
        d_order[d_offsets[s.y] + r.y] = base + 1;
        d_order[d_offsets[s.z] + r.z] = base + 2;
        d_order[d_offsets[s.w] + r.w] = base + 3;
    } else {
        for (int j = base; j < n; j++)
            d_order[d_offsets[seg[j]] + d_rank[j]] = j;
    }
}

// ---------------------------------------------------------------------------
// Kernel A: dense 3-split bf16 wmma GEMM, original row order (NO gather).
// 256 threads, 128 rows/CTA, accumulators stored DIRECTLY to global d_h
// (padded, so no tail handling). smem = W(18KB) + A(36KB) = 55KB -> 3+ CTA/SM.
// b_fc cancels after normalization -> h = x @ W only.
// ---------------------------------------------------------------------------
#define LDA   72
#define SM_WH 0
#define SM_WL 9216
#define SM_AH 18432
#define SM_AL 36864
#define GEMM_SMEM 55296

typedef wmma::fragment<wmma::matrix_a, 16, 16, 16, __nv_bfloat16, wmma::row_major> FragA;
typedef wmma::fragment<wmma::matrix_b, 16, 16, 16, __nv_bfloat16, wmma::row_major> FragB;
typedef wmma::fragment<wmma::accumulator, 16, 16, 16, float> FragC;

__global__ __launch_bounds__(256, 3) void gemm_dense_kernel(const float* __restrict__ x,
                                                            int n) {
    extern __shared__ char smem[];
    int t = threadIdx.x, w = t >> 5;
    int base = blockIdx.x * 128;

    // W hi/lo -> padded smem (stride 72 bf16); hot in L2
    for (int i = t; i < 2048; i += 256) {
        int k = i >> 5, j = i & 31;
        int b2 = k * (LDA * 2) + 4 * j;
        *reinterpret_cast<uint32_t*>(smem + SM_WH + b2) = d_Wh32[i];
        *reinterpret_cast<uint32_t*>(smem + SM_WL + b2) = d_Wl32[i];
    }

    // stage 128 dense rows -> bf16 hi/lo (row sr, half sq)
    {
        int sr = t >> 1, sq = t & 1;
        int row = base + sr;
        float4 v[8];
        if (row < n) {
            const float4* xr = reinterpret_cast<const float4*>(x + (size_t)row * 64 + 32 * sq);
#pragma unroll
            for (int i = 0; i < 8; i++) v[i] = xr[i];
        } else {
#pragma unroll
            for (int i = 0; i < 8; i++) v[i] = make_float4(0.f, 0.f, 0.f, 0.f);
        }
        uint32_t uh[16], ul[16];
#pragma unroll
        for (int i = 0; i < 8; i++) {
            float f0 = v[i].x, f1 = v[i].y, f2 = v[i].z, f3 = v[i].w;
            __nv_bfloat16 h0 = __float2bfloat16(f0), h1 = __float2bfloat16(f1);
            __nv_bfloat16 h2 = __float2bfloat16(f2), h3 = __float2bfloat16(f3);
            __nv_bfloat16 l0 = __float2bfloat16(f0 - __bfloat162float(h0));
            __nv_bfloat16 l1 = __float2bfloat16(f1 - __bfloat162float(h1));
            __nv_bfloat16 l2 = __float2bfloat16(f2 - __bfloat162float(h2));
            __nv_bfloat16 l3 = __float2bfloat16(f3 - __bfloat162float(h3));
            uh[2 * i]     = (uint32_t)__bfloat16_as_ushort(h0) | ((uint32_t)__bfloat16_as_ushort(h1) << 16);
            uh[2 * i + 1] = (uint32_t)__bfloat16_as_ushort(h2) | ((uint32_t)__bfloat16_as_ushort(h3) << 16);
            ul[2 * i]     = (uint32_t)__bfloat16_as_ushort(l0) | ((uint32_t)__bfloat16_as_ushort(l1) << 16);
            ul[2 * i + 1] = (uint32_t)__bfloat16_as_ushort(l2) | ((uint32_t)__bfloat16_as_ushort(l3) << 16);
        }
        int b2 = sr * (LDA * 2) + 64 * sq;
#pragma unroll
        for (int i = 0; i < 4; i++) {
            *reinterpret_cast<uint4*>(smem + SM_AH + b2 + 16 * i) =
                make_uint4(uh[4 * i], uh[4 * i + 1], uh[4 * i + 2], uh[4 * i + 3]);
            *reinterpret_cast<uint4*>(smem + SM_AL + b2 + 16 * i) =
                make_uint4(ul[4 * i], ul[4 * i + 1], ul[4 * i + 2], ul[4 * i + 3]);
        }
    }
    __syncthreads();

    // warp w: rows 16w..16w+15, 3 splits, store straight to global d_h
    {
        const __nv_bfloat16* Ah = reinterpret_cast<const __nv_bfloat16*>(smem + SM_AH);
        const __nv_bfloat16* Al = reinterpret_cast<const __nv_bfloat16*>(smem + SM_AL);
        const __nv_bfloat16* Wh = reinterpret_cast<const __nv_bfloat16*>(smem + SM_WH);
        const __nv_bfloat16* Wl = reinterpret_cast<const __nv_bfloat16*>(smem + SM_WL);

        FragA a[4];
        FragC acc[4];
#pragma unroll
        for (int ct = 0; ct < 4; ct++) wmma::fill_fragment(acc[ct], 0.f);
#pragma unroll
        for (int s = 0; s < 3; s++) {
            const __nv_bfloat16* A = (s < 2) ? Ah : Al;
            const __nv_bfloat16* B = (s == 1) ? Wl : Wh;
            if (s != 1) {  // s==1 reuses s==0's A fragments
#pragma unroll
                for (int k4 = 0; k4 < 4; k4++)
                    wmma::load_matrix_sync(a[k4], A + (size_t)(16 * w) * LDA + 16 * k4, LDA);
            }
#pragma unroll
            for (int ct = 0; ct < 4; ct++) {
#pragma unroll
                for (int k4 = 0; k4 < 4; k4++) {
                    FragB b;
                    wmma::load_matrix_sync(b, B + (size_t)(16 * k4) * LDA + 16 * ct, LDA);
                    wmma::mma_sync(acc[ct], a[k4], b, acc[ct]);
                }
            }
        }
        float* hout = d_h + (size_t)(base + 16 * w) * 64;
#pragma unroll
        for (int ct = 0; ct < 4; ct++)
            wmma::store_matrix_sync(hout + 16 * ct, acc[ct], 64, wmma::mem_row_major);
    }
}

// ---------------------------------------------------------------------------
// Kernel B: per-group stats + apply. 256 threads, ~1KB smem -> high occupancy.
// Phase 1: gather-read h rows (float4, coalesced 256B/row), reduce in regs.
// Phase 2: scale/shift. Phase 3: re-read h (L2-hot), apply ReLU, write out.
// ---------------------------------------------------------------------------
__global__ __launch_bounds__(256, 8) void stats_apply_kernel(float* __restrict__ out) {
    __shared__ float sSum[64], sSq[64], sScale[64], sShift[64];
    int t = threadIdx.x;
    int g   = blockIdx.x;
    int off = d_offsets[g];
    int cnt = d_offsets[g + 1] - off;
    if (cnt == 0) return;

    if (t < 64) { sSum[t] = 0.f; sSq[t] = 0.f; }
    __syncthreads();

    int c4 = t & 15, rq = t >> 4;   // channel-quad, row phase (16 rows/step)
    const float4* h4 = reinterpret_cast<const float4*>(d_h);

    float4 s1 = make_float4(0.f, 0.f, 0.f, 0.f);
    float4 s2 = make_float4(0.f, 0.f, 0.f, 0.f);
    for (int j = rq; j < cnt; j += 16) {
        int gi = __ldg(&d_order[off + j]);
        float4 v = h4[(size_t)gi * 16 + c4];
        s1.x += v.x; s2.x = fmaf(v.x, v.x, s2.x);
        s1.y += v.y; s2.y = fmaf(v.y, v.y, s2.y);
        s1.z += v.z; s2.z = fmaf(v.z, v.z, s2.z);
        s1.w += v.w; s2.w = fmaf(v.w, v.w, s2.w);
    }
    atomicAdd(&sSum[4 * c4 + 0], s1.x); atomicAdd(&sSq[4 * c4 + 0], s2.x);
    atomicAdd(&sSum[4 * c4 + 1], s1.y); atomicAdd(&sSq[4 * c4 + 1], s2.y);
    atomicAdd(&sSum[4 * c4 + 2], s1.z); atomicAdd(&sSq[4 * c4 + 2], s2.z);
    atomicAdd(&sSum[4 * c4 + 3], s1.w); atomicAdd(&sSq[4 * c4 + 3], s2.w);
    __syncthreads();

    if (t < 64) {
        float inv  = 1.0f / (float)cnt;
        float mean = sSum[t] * inv;
        float var  = fmaxf(sSq[t] * inv - mean * mean, 0.f);
        float sc   = __ldg(&d_sig[(size_t)g * 64 + t]) * rsqrtf(var + 1e-14f);
        sScale[t] = sc;
        sShift[t] = __ldg(&d_mu[(size_t)g * 64 + t]) - mean * sc;
    }
    __syncthreads();

    float4 sc4 = reinterpret_cast<float4*>(sScale)[c4];
    float4 sh4 = reinterpret_cast<float4*>(sShift)[c4];
    float4* o4 = reinterpret_cast<float4*>(out);
    for (int j = rq; j < cnt; j += 16) {
        int gi = __ldg(&d_order[off + j]);
        float4 v = h4[(size_t)gi * 16 + c4];   // L2 hit (read in phase 1)
        float4 o;
        o.x = fmaxf(fmaf(v.x, sc4.x, sh4.x), 0.f);
        o.y = fmaxf(fmaf(v.y, sc4.y, sh4.y), 0.f);
        o.z = fmaxf(fmaf(v.z, sc4.z, sh4.z), 0.f);
        o.w = fmaxf(fmaf(v.w, sc4.w, sh4.w), 0.f);
        o4[(size_t)gi * 16 + c4] = o;
    }
}

// ---------------------------------------------------------------------------
extern "C" void kernel_launch(void* const* d_in, const int* in_sizes, int n_in,
                              void* d_out, int out_size) {
    int wi = (n_in >= 10) ? 4 : 3;
    const float* x    = (const float*)d_in[0];
    const float* feat = (const float*)d_in[1];
    const int*   seg  = (const int*)d_in[2];
    const float* Wfc  = (const float*)d_in[wi + 0];
    const float* Wmu  = (const float*)d_in[wi + 2];
    const float* bmu  = (const float*)d_in[wi + 3];
    const float* Wsg  = (const float*)d_in[wi + 4];
    const float* bsg  = (const float*)d_in[wi + 5];
    float* out = (float*)d_out;

    int n = in_sizes[0] / 64;
    int G = in_sizes[1] / 128;

    cudaFuncSetAttribute(gemm_dense_kernel, cudaFuncAttributeMaxDynamicSharedMemorySize,
                         GEMM_SMEM);

    int q = (n + 3) / 4;
    musig_init_kernel<<<(G + 3) / 4, 256>>>(feat, Wmu, bmu, Wsg, bsg, Wfc, G);
    gemm_dense_kernel<<<(n + 127) / 128, 256, GEMM_SMEM>>>(x, n);
    hist_kernel<<<(q + 255) / 256, 256>>>(seg, n);
    scan_kernel<<<1, 1024>>>(G);
    scatter_kernel<<<(q + 255) / 256, 256>>>(seg, n);
    stats_apply_kernel<<<G, 256>>>(out);
}

// round 15
// speedup vs baseline: 1.2547x; 1.0762x over previous
#include <cuda_runtime.h>
#include <cuda_bf16.h>
#include <mma.h>
#include <stdint.h>

using namespace nvcuda;

// Problem constants (fixed benchmark): N=1e6, IN_C=OUT_C=64, FEAT_C=128, G=4096
#define N_MAX 1000000
#define G_MAX 4096

__device__ int      d_count[G_MAX];
__device__ int      d_offsets[G_MAX + 1];
__device__ int      d_rank[N_MAX];
__device__ int      d_order[N_MAX];
__device__ float    d_mu[G_MAX * 64];
__device__ float    d_sig[G_MAX * 64];
// bf16 hi/lo images of W_fc [64k][64n], packed as bf16-pairs along n: [k][32] u32
__device__ uint32_t d_Wh32[2048];
__device__ uint32_t d_Wl32[2048];
// h = x @ W in GROUP-SORTED row order, padded to a multiple of 128 rows
__device__ float    d_h[(N_MAX + 256) * 64];

// ---------------------------------------------------------------------------
// Preprocessing
// ---------------------------------------------------------------------------
__global__ void musig_init_kernel(const float* __restrict__ feat,
                                  const float* __restrict__ Wmu, const float* __restrict__ bmu,
                                  const float* __restrict__ Wsg, const float* __restrict__ bsg,
                                  const float* __restrict__ Wfc, int G) {
    int gid = blockIdx.x * blockDim.x + threadIdx.x;
    if (gid < G) d_count[gid] = 0;
    if (gid < 2048) {  // pair (k, 2j)/(k, 2j+1)
        int k = gid >> 5, j = gid & 31;
        float w0 = Wfc[k * 64 + 2 * j];
        float w1 = Wfc[k * 64 + 2 * j + 1];
        __nv_bfloat16 h0 = __float2bfloat16(w0);
        __nv_bfloat16 h1 = __float2bfloat16(w1);
        __nv_bfloat16 l0 = __float2bfloat16(w0 - __bfloat162float(h0));
        __nv_bfloat16 l1 = __float2bfloat16(w1 - __bfloat162float(h1));
        d_Wh32[gid] = (uint32_t)__bfloat16_as_ushort(h0) | ((uint32_t)__bfloat16_as_ushort(h1) << 16);
        d_Wl32[gid] = (uint32_t)__bfloat16_as_ushort(l0) | ((uint32_t)__bfloat16_as_ushort(l1) << 16);
    }

    __shared__ float sF[4][128];
    int t  = threadIdx.x;
    int g0 = blockIdx.x * 4;
    for (int i = t; i < 512; i += 256) {
        int gl = i >> 7, k = i & 127;
        int g  = g0 + gl;
        sF[gl][k] = (g < G) ? feat[(size_t)g * 128 + k] : 0.f;
    }
    __syncthreads();
    int gl = t >> 6, c = t & 63;
    int g  = g0 + gl;
    if (g >= G) return;
    float am = bmu[c], as = bsg[c];
#pragma unroll 4
    for (int k = 0; k < 128; k++) {
        float f = sF[gl][k];
        am = fmaf(f, Wmu[k * 64 + c], am);
        as = fmaf(f, Wsg[k * 64 + c], as);
    }
    d_mu[(size_t)g * 64 + c]  = am;
    d_sig[(size_t)g * 64 + c] = as;
}

// histogram; atomic's return value IS the row's rank within its group
__global__ void hist_kernel(const int* __restrict__ seg, int n) {
    int i = blockIdx.x * blockDim.x + threadIdx.x;
    int base = i * 4;
    if (base + 3 < n) {
        int4 s = *reinterpret_cast<const int4*>(seg + base);
        int r0 = atomicAdd(&d_count[s.x], 1);
        int r1 = atomicAdd(&d_count[s.y], 1);
        int r2 = atomicAdd(&d_count[s.z], 1);
        int r3 = atomicAdd(&d_count[s.w], 1);
        *reinterpret_cast<int4*>(d_rank + base) = make_int4(r0, r1, r2, r3);
    } else {
        for (int j = base; j < n; j++)
            d_rank[j] = atomicAdd(&d_count[seg[j]], 1);
    }
}

__global__ void scan_kernel(int G) {
    __shared__ int wsum[32];
    __shared__ int wpre[32];
    const unsigned full = 0xffffffffu;
    int t = threadIdx.x, lane = t & 31, w = t >> 5;
    int v[4];
    int s = 0;
#pragma unroll
    for (int i = 0; i < 4; i++) {
        int g = 4 * t + i;
        v[i] = (g < G) ? d_count[g] : 0;
        s += v[i];
    }
    int sc = s;
#pragma unroll
    for (int off = 1; off < 32; off <<= 1) {
        int o = __shfl_up_sync(full, sc, off);
        if (lane >= off) sc += o;
    }
    if (lane == 31) wsum[w] = sc;
    __syncthreads();
    if (w == 0) {
        int ws = wsum[lane];
        int p = ws;
#pragma unroll
        for (int off = 1; off < 32; off <<= 1) {
            int o = __shfl_up_sync(full, p, off);
            if (lane >= off) p += o;
        }
        wpre[lane] = p - ws;
    }
    __syncthreads();
    int excl = wpre[w] + sc - s;
#pragma unroll
    for (int i = 0; i < 4; i++) {
        int g = 4 * t + i;
        if (g < G) {
            d_offsets[g] = excl;
            excl += v[i];
        }
    }
    if (t == 1023) d_offsets[G] = excl;
}

// no atomic: position = group offset + precomputed rank
__global__ void scatter_kernel(const int* __restrict__ seg, int n) {
    int i = blockIdx.x * blockDim.x + threadIdx.x;
    int base = i * 4;
    if (base + 3 < n) {
        int4 s = *reinterpret_cast<const int4*>(seg + base);
        int4 r = *reinterpret_cast<const int4*>(d_rank + base);
        d_order[d_offsets[s.x] + r.x] = base;
        d_order[d_offsets[s.y] + r.y] = base + 1;
        d_order[d_offsets[s.z] + r.z] = base + 2;
        d_order[d_offsets[s.w] + r.w] = base + 3;
    } else {
        for (int j = base; j < n; j++)
            d_order[d_offsets[seg[j]] + d_rank[j]] = j;
    }
}

// ---------------------------------------------------------------------------
// Kernel A: 3-split bf16 wmma GEMM over GROUP-SORTED rows (gather x via
// d_order), h written DENSE in sorted order -> downstream reads are streaming.
// 256 threads, 128 rows/CTA. smem = W(18KB) + A(36KB) = 55KB.
// b_fc cancels after normalization -> h = x @ W only.
// ---------------------------------------------------------------------------
#define LDA   72
#define SM_WH 0
#define SM_WL 9216
#define SM_AH 18432
#define SM_AL 36864
#define GEMM_SMEM 55296

typedef wmma::fragment<wmma::matrix_a, 16, 16, 16, __nv_bfloat16, wmma::row_major> FragA;
typedef wmma::fragment<wmma::matrix_b, 16, 16, 16, __nv_bfloat16, wmma::row_major> FragB;
typedef wmma::fragment<wmma::accumulator, 16, 16, 16, float> FragC;

__global__ __launch_bounds__(256, 2) void gemm_sorted_kernel(const float* __restrict__ x,
                                                             int n) {
    extern __shared__ char smem[];
    int t = threadIdx.x, w = t >> 5;
    int base = blockIdx.x * 128;

    // W hi/lo -> padded smem (stride 72 bf16); hot in L2
    for (int i = t; i < 2048; i += 256) {
        int k = i >> 5, j = i & 31;
        int b2 = k * (LDA * 2) + 4 * j;
        *reinterpret_cast<uint32_t*>(smem + SM_WH + b2) = d_Wh32[i];
        *reinterpret_cast<uint32_t*>(smem + SM_WL + b2) = d_Wl32[i];
    }

    // stage 128 sorted rows -> bf16 hi/lo (row sr, half sq); gather via d_order
    {
        int sr = t >> 1, sq = t & 1;
        int row = base + sr;
        float4 v[8];
        if (row < n) {
            int gi = __ldg(&d_order[row]);
            const float4* xr = reinterpret_cast<const float4*>(x + (size_t)gi * 64 + 32 * sq);
#pragma unroll
            for (int i = 0; i < 8; i++) v[i] = xr[i];
        } else {
#pragma unroll
            for (int i = 0; i < 8; i++) v[i] = make_float4(0.f, 0.f, 0.f, 0.f);
        }
        uint32_t uh[16], ul[16];
#pragma unroll
        for (int i = 0; i < 8; i++) {
            float f0 = v[i].x, f1 = v[i].y, f2 = v[i].z, f3 = v[i].w;
            __nv_bfloat16 h0 = __float2bfloat16(f0), h1 = __float2bfloat16(f1);
            __nv_bfloat16 h2 = __float2bfloat16(f2), h3 = __float2bfloat16(f3);
            __nv_bfloat16 l0 = __float2bfloat16(f0 - __bfloat162float(h0));
            __nv_bfloat16 l1 = __float2bfloat16(f1 - __bfloat162float(h1));
            __nv_bfloat16 l2 = __float2bfloat16(f2 - __bfloat162float(h2));
            __nv_bfloat16 l3 = __float2bfloat16(f3 - __bfloat162float(h3));
            uh[2 * i]     = (uint32_t)__bfloat16_as_ushort(h0) | ((uint32_t)__bfloat16_as_ushort(h1) << 16);
            uh[2 * i + 1] = (uint32_t)__bfloat16_as_ushort(h2) | ((uint32_t)__bfloat16_as_ushort(h3) << 16);
            ul[2 * i]     = (uint32_t)__bfloat16_as_ushort(l0) | ((uint32_t)__bfloat16_as_ushort(l1) << 16);
            ul[2 * i + 1] = (uint32_t)__bfloat16_as_ushort(l2) | ((uint32_t)__bfloat16_as_ushort(l3) << 16);
        }
        int b2 = sr * (LDA * 2) + 64 * sq;
#pragma unroll
        for (int i = 0; i < 4; i++) {
            *reinterpret_cast<uint4*>(smem + SM_AH + b2 + 16 * i) =
                make_uint4(uh[4 * i], uh[4 * i + 1], uh[4 * i + 2], uh[4 * i + 3]);
            *reinterpret_cast<uint4*>(smem + SM_AL + b2 + 16 * i) =
                make_uint4(ul[4 * i], ul[4 * i + 1], ul[4 * i + 2], ul[4 * i + 3]);
        }
    }
    __syncthreads();

    // warp w: rows 16w..16w+15. A fragments resident; each Wh fragment feeds
    // both ah*Wh and al*Wh (B smem loads: 32 instead of 48).
    {
        const __nv_bfloat16* Ah = reinterpret_cast<const __nv_bfloat16*>(smem + SM_AH);
        const __nv_bfloat16* Al = reinterpret_cast<const __nv_bfloat16*>(smem + SM_AL);
        const __nv_bfloat16* Wh = reinterpret_cast<const __nv_bfloat16*>(smem + SM_WH);
        const __nv_bfloat16* Wl = reinterpret_cast<const __nv_bfloat16*>(smem + SM_WL);

        FragA ah[4], al[4];
#pragma unroll
        for (int k4 = 0; k4 < 4; k4++) {
            wmma::load_matrix_sync(ah[k4], Ah + (size_t)(16 * w) * LDA + 16 * k4, LDA);
            wmma::load_matrix_sync(al[k4], Al + (size_t)(16 * w) * LDA + 16 * k4, LDA);
        }
        FragC acc[4];
#pragma unroll
        for (int ct = 0; ct < 4; ct++) wmma::fill_fragment(acc[ct], 0.f);
#pragma unroll
        for (int ct = 0; ct < 4; ct++) {
#pragma unroll
            for (int k4 = 0; k4 < 4; k4++) {
                FragB bh;
                wmma::load_matrix_sync(bh, Wh + (size_t)(16 * k4) * LDA + 16 * ct, LDA);
                wmma::mma_sync(acc[ct], ah[k4], bh, acc[ct]);
                wmma::mma_sync(acc[ct], al[k4], bh, acc[ct]);
            }
#pragma unroll
            for (int k4 = 0; k4 < 4; k4++) {
                FragB bl;
                wmma::load_matrix_sync(bl, Wl + (size_t)(16 * k4) * LDA + 16 * ct, LDA);
                wmma::mma_sync(acc[ct], ah[k4], bl, acc[ct]);
            }
        }
        float* hout = d_h + (size_t)(base + 16 * w) * 64;
#pragma unroll
        for (int ct = 0; ct < 4; ct++)
            wmma::store_matrix_sync(hout + 16 * ct, acc[ct], 64, wmma::mem_row_major);
    }
}

// ---------------------------------------------------------------------------
// Kernel B: per-group stats + apply. h is SORTED -> both reads are contiguous
// streams; only the final out write scatters (256B full rows).
// 256 threads, ~1KB smem -> high occupancy.
// ---------------------------------------------------------------------------
__global__ __launch_bounds__(256, 8) void stats_apply_kernel(float* __restrict__ out) {
    __shared__ float sSum[64], sSq[64], sScale[64], sShift[64];
    int t = threadIdx.x;
    int g   = blockIdx.x;
    int off = d_offsets[g];
    int cnt = d_offsets[g + 1] - off;
    if (cnt == 0) return;

    if (t < 64) { sSum[t] = 0.f; sSq[t] = 0.f; }
    __syncthreads();

    int c4 = t & 15, rq = t >> 4;   // channel-quad, row phase (16 rows/step)
    const float4* h4 = reinterpret_cast<const float4*>(d_h);

    // ---- stats: contiguous stream over the group's h rows ----
    float4 s1 = make_float4(0.f, 0.f, 0.f, 0.f);
    float4 s2 = make_float4(0.f, 0.f, 0.f, 0.f);
    for (int j = rq; j < cnt; j += 16) {
        float4 v = h4[(size_t)(off + j) * 16 + c4];
        s1.x += v.x; s2.x = fmaf(v.x, v.x, s2.x);
        s1.y += v.y; s2.y = fmaf(v.y, v.y, s2.y);
        s1.z += v.z; s2.z = fmaf(v.z, v.z, s2.z);
        s1.w += v.w; s2.w = fmaf(v.w, v.w, s2.w);
    }
    atomicAdd(&sSum[4 * c4 + 0], s1.x); atomicAdd(&sSq[4 * c4 + 0], s2.x);
    atomicAdd(&sSum[4 * c4 + 1], s1.y); atomicAdd(&sSq[4 * c4 + 1], s2.y);
    atomicAdd(&sSum[4 * c4 + 2], s1.z); atomicAdd(&sSq[4 * c4 + 2], s2.z);
    atomicAdd(&sSum[4 * c4 + 3], s1.w); atomicAdd(&sSq[4 * c4 + 3], s2.w);
    __syncthreads();

    if (t < 64) {
        float inv  = 1.0f / (float)cnt;
        float mean = sSum[t] * inv;
        float var  = fmaxf(sSq[t] * inv - mean * mean, 0.f);
        float sc   = __ldg(&d_sig[(size_t)g * 64 + t]) * rsqrtf(var + 1e-14f);
        sScale[t] = sc;
        sShift[t] = __ldg(&d_mu[(size_t)g * 64 + t]) - mean * sc;
    }
    __syncthreads();

    // ---- apply: re-stream h (L2-hot), scatter-write out rows ----
    float4 sc4 = reinterpret_cast<float4*>(sScale)[c4];
    float4 sh4 = reinterpret_cast<float4*>(sShift)[c4];
    float4* o4 = reinterpret_cast<float4*>(out);
    for (int j = rq; j < cnt; j += 16) {
        int gi = __ldg(&d_order[off + j]);
        float4 v = h4[(size_t)(off + j) * 16 + c4];
        float4 o;
        o.x = fmaxf(fmaf(v.x, sc4.x, sh4.x), 0.f);
        o.y = fmaxf(fmaf(v.y, sc4.y, sh4.y), 0.f);
        o.z = fmaxf(fmaf(v.z, sc4.z, sh4.z), 0.f);
        o.w = fmaxf(fmaf(v.w, sc4.w, sh4.w), 0.f);
        o4[(size_t)gi * 16 + c4] = o;
    }
}

// ---------------------------------------------------------------------------
extern "C" void kernel_launch(void* const* d_in, const int* in_sizes, int n_in,
                              void* d_out, int out_size) {
    int wi = (n_in >= 10) ? 4 : 3;
    const float* x    = (const float*)d_in[0];
    const float* feat = (const float*)d_in[1];
    const int*   seg  = (const int*)d_in[2];
    const float* Wfc  = (const float*)d_in[wi + 0];
    const float* Wmu  = (const float*)d_in[wi + 2];
    const float* bmu  = (const float*)d_in[wi + 3];
    const float* Wsg  = (const float*)d_in[wi + 4];
    const float* bsg  = (const float*)d_in[wi + 5];
    float* out = (float*)d_out;

    int n = in_sizes[0] / 64;
    int G = in_sizes[1] / 128;

    cudaFuncSetAttribute(gemm_sorted_kernel, cudaFuncAttributeMaxDynamicSharedMemorySize,
                         GEMM_SMEM);

    int q = (n + 3) / 4;
    musig_init_kernel<<<(G + 3) / 4, 256>>>(feat, Wmu, bmu, Wsg, bsg, Wfc, G);
    hist_kernel<<<(q + 255) / 256, 256>>>(seg, n);
    scan_kernel<<<1, 1024>>>(G);
    scatter_kernel<<<(q + 255) / 256, 256>>>(seg, n);
    gemm_sorted_kernel<<<(n + 127) / 128, 256, GEMM_SMEM>>>(x, n);
    stats_apply_kernel<<<G, 256>>>(out);
}